// round 1
// baseline (speedup 1.0000x reference)
#include <cuda_runtime.h>
#include <cstdint>
#include <cmath>

// Problem sizes
//  B=64, T=512, E=256, U=256; gates 4U=1024 per direction.

__device__ float g_Z[2ull * 512 * 64 * 1024];     // [dir][t][b][u*4+gate], 256 MB scratch
__device__ unsigned char g_mask[64 * 512];         // [b][t]

// ---------------------------------------------------------------------------
// Mask kernel: mask[b][t] = any(x[b,t,:] != 0)
// ---------------------------------------------------------------------------
__global__ void mask_kernel(const float* __restrict__ x)
{
    int gw   = (blockIdx.x * blockDim.x + threadIdx.x) >> 5;   // row = b*512+t
    int lane = threadIdx.x & 31;
    if (gw >= 64 * 512) return;
    const float4* p = reinterpret_cast<const float4*>(x + (size_t)gw * 256);
    float4 a = p[lane];
    float4 b = p[lane + 32];
    bool nz = (a.x != 0.f) || (a.y != 0.f) || (a.z != 0.f) || (a.w != 0.f) ||
              (b.x != 0.f) || (b.y != 0.f) || (b.z != 0.f) || (b.w != 0.f);
    unsigned m = __ballot_sync(0xffffffffu, nz);
    if (lane == 0) g_mask[gw] = (m != 0u) ? 1 : 0;
}

// ---------------------------------------------------------------------------
// Input GEMM: Z[m][n] = sum_k x'[m][k] * Wk_cat[k][n] + bias[n]
//   m = t*64 + b  (M = 32768),  n in [0,2048): dir = n>>10, col = n&1023
//   A[m][k] = x[b][t][k]
//   Output permuted to g_Z[dir][t][b][u*4 + g]  (g = col>>8, u = col&255)
// 128x128 tile, 8-deep K slices, 256 threads, 8x8 microtile.
// ---------------------------------------------------------------------------
__global__ __launch_bounds__(256) void gemm_kernel(
    const float* __restrict__ x,
    const float* __restrict__ Wk_f, const float* __restrict__ Wk_b,
    const float* __restrict__ b_f,  const float* __restrict__ b_b)
{
    __shared__ float As[8][132];
    __shared__ float Bs[8][128];

    const int tid = threadIdx.x;
    const int mt  = blockIdx.x * 128;
    const int nt  = blockIdx.y * 128;
    const int tx  = tid & 15, ty = tid >> 4;

    // A-load mapping: 128 rows x 8 k = 256 float4, one per thread
    const int arow = tid >> 1, akq = (tid & 1) * 4;
    const int am = mt + arow;
    const int ab = am & 63, at = am >> 6;
    const float* aptr = x + ((size_t)ab * 512 + at) * 256 + akq;

    // B-load mapping: 8 k x 128 n = 256 float4
    const int bk = tid >> 5, bn = (tid & 31) * 4;
    const int n0 = nt + bn;
    const float* Wk  = (n0 >= 1024) ? Wk_b : Wk_f;
    const float* bptr = Wk + (n0 & 1023);

    float acc[8][8];
#pragma unroll
    for (int i = 0; i < 8; i++)
#pragma unroll
        for (int j = 0; j < 8; j++) acc[i][j] = 0.f;

    for (int k0 = 0; k0 < 256; k0 += 8) {
        float4 av = *reinterpret_cast<const float4*>(aptr + k0);
        float4 bv = *reinterpret_cast<const float4*>(bptr + (size_t)(k0 + bk) * 1024);
        __syncthreads();
        As[akq + 0][arow] = av.x;
        As[akq + 1][arow] = av.y;
        As[akq + 2][arow] = av.z;
        As[akq + 3][arow] = av.w;
        *reinterpret_cast<float4*>(&Bs[bk][bn]) = bv;
        __syncthreads();
#pragma unroll
        for (int kk = 0; kk < 8; kk++) {
            float a[8], b[8];
            *reinterpret_cast<float4*>(&a[0]) = *reinterpret_cast<const float4*>(&As[kk][ty * 8]);
            *reinterpret_cast<float4*>(&a[4]) = *reinterpret_cast<const float4*>(&As[kk][ty * 8 + 4]);
            *reinterpret_cast<float4*>(&b[0]) = *reinterpret_cast<const float4*>(&Bs[kk][tx * 8]);
            *reinterpret_cast<float4*>(&b[4]) = *reinterpret_cast<const float4*>(&Bs[kk][tx * 8 + 4]);
#pragma unroll
            for (int i = 0; i < 8; i++)
#pragma unroll
                for (int j = 0; j < 8; j++)
                    acc[i][j] = fmaf(a[i], b[j], acc[i][j]);
        }
    }

    // Epilogue: add bias, permute-store to g_Z
#pragma unroll
    for (int i = 0; i < 8; i++) {
        const int m  = mt + ty * 8 + i;
        const int bb = m & 63, tt = m >> 6;
#pragma unroll
        for (int j = 0; j < 8; j++) {
            const int n   = nt + tx * 8 + j;
            const int dir = n >> 10;
            const int col = n & 1023;
            const int g   = col >> 8, u = col & 255;
            const float bias = (dir ? b_b : b_f)[col];
            g_Z[(((size_t)dir * 512 + tt) * 64 + bb) * 1024 + (u << 2) + g] = acc[i][j] + bias;
        }
    }
}

// ---------------------------------------------------------------------------
// Recurrence kernel. 128 CTAs = 2 dirs x 8 batch-groups x 8 cluster ranks.
// Cluster of 8 CTAs = one (direction, 8-batch group). Rank r owns u-range
// [r*32, (r+1)*32). Wr slice (256 x 32u x 4gates = 128 KB fp32) lives in SMEM
// for the whole kernel. h (8 batches x 256 u, double-buffered) is exchanged
// each step via DSMEM stores + barrier.cluster.
// Thread layout: warp w (0..7) -> u_local in [w*4, w*4+4); lane -> (b=lane&7,
// uoff=lane>>3). Each thread owns one (b, u) pair: 4 gate accumulators + c.
// ---------------------------------------------------------------------------
__device__ __forceinline__ uint32_t smem_u32(const void* p)
{
    uint32_t a;
    asm("{ .reg .u64 t; cvta.to.shared.u64 t, %1; cvt.u32.u64 %0, t; }"
        : "=r"(a) : "l"(p));
    return a;
}
__device__ __forceinline__ uint32_t mapa_rank(uint32_t addr, uint32_t rank)
{
    uint32_t r;
    asm("mapa.shared::cluster.u32 %0, %1, %2;" : "=r"(r) : "r"(addr), "r"(rank));
    return r;
}
__device__ __forceinline__ void st_cluster_f32(uint32_t addr, float v)
{
    asm volatile("st.shared::cluster.f32 [%0], %1;" :: "r"(addr), "f"(v) : "memory");
}
#define CLUSTER_SYNC() do { \
    asm volatile("barrier.cluster.arrive.aligned;" ::: "memory"); \
    asm volatile("barrier.cluster.wait.aligned;"   ::: "memory"); \
} while (0)

// SMEM layout (floats): Wr_s [256][32][4] = 32768 ; h_s [2][8][260] = 4160 ;
// then mask bytes [8][512] = 4096 B.
#define REC_SMEM_BYTES ((32768 + 4160) * 4 + 4096)

__global__ void __cluster_dims__(8, 1, 1) __launch_bounds__(256, 1)
lstm_rec_kernel(const float* __restrict__ Wr_f, const float* __restrict__ Wr_b,
                float* __restrict__ out)
{
    extern __shared__ float sm[];
    float* Wr_s = sm;                       // 32768 floats
    float* h_s  = sm + 32768;               // 2*8*260 floats (row pad 260 kills bank conflicts)
    unsigned char* m_s = reinterpret_cast<unsigned char*>(sm + 32768 + 4160);

    const int tid  = threadIdx.x;
    const int bx   = blockIdx.x;
    const int dir  = bx >> 6;
    const int rank = bx & 7;
    const int bg   = (bx & 63) >> 3;
    const int w    = tid >> 5, lane = tid & 31;
    const int b    = lane & 7, uoff = lane >> 3;
    const int ul   = w * 4 + uoff;            // 0..31
    const int ug   = (rank << 5) + ul;        // 0..255
    const int b_global = (bg << 3) + b;

    // Load Wr slice: smem [k][ul][gate] as float4 per (k,ul)
    const float* Wr = dir ? Wr_b : Wr_f;
    for (int i = tid; i < 256 * 32; i += 256) {
        const int k = i >> 5, ux = i & 31;
        const int u = (rank << 5) + ux;
        float4 v;
        v.x = Wr[k * 1024 + u];
        v.y = Wr[k * 1024 + 256 + u];
        v.z = Wr[k * 1024 + 512 + u];
        v.w = Wr[k * 1024 + 768 + u];
        reinterpret_cast<float4*>(Wr_s)[(k << 5) + ux] = v;
    }
    // Mask for this CTA's 8 batches
    for (int i = tid; i < 8 * 512; i += 256)
        m_s[i] = g_mask[((bg << 3) + (i >> 9)) * 512 + (i & 511)];
    // Zero both h buffers
    for (int i = tid; i < 2 * 8 * 260; i += 256) h_s[i] = 0.f;

    // Precompute remote SMEM addresses for the h broadcast (both buffers x 8 ranks)
    const uint32_t base = smem_u32(h_s);
    const uint32_t l0 = base + ((uint32_t)((0 * 8 + b) * 260 + ug) << 2);
    const uint32_t l1 = base + ((uint32_t)((1 * 8 + b) * 260 + ug) << 2);
    uint32_t r0[8], r1[8];
#pragma unroll
    for (int r = 0; r < 8; r++) { r0[r] = mapa_rank(l0, r); r1[r] = mapa_rank(l1, r); }

    CLUSTER_SYNC();   // all h buffers initialized cluster-wide

    float cst = 0.f;
    float hlast = 0.f;
    int cur = 0;

    const float4* Z4 = reinterpret_cast<const float4*>(g_Z);
    const int t0 = dir ? 511 : 0;
    float4 znext = __ldg(&Z4[(((size_t)dir * 512 + t0) * 64 + b_global) * 256 + ug]);

    for (int step = 0; step < 512; step++) {
        const int t = dir ? (511 - step) : step;
        float4 acc = znext;                       // x@Wk + bias for (t, b, u, gates)
        if (step < 511) {                         // prefetch next step's z (hidden by k-loop)
            const int tn = dir ? (510 - step) : (step + 1);
            znext = __ldg(&Z4[(((size_t)dir * 512 + tn) * 64 + b_global) * 256 + ug]);
        }

        const float*  hrow = h_s + (cur * 8 + b) * 260;
        const float4* wrp  = reinterpret_cast<const float4*>(Wr_s) + ul;
#pragma unroll 8
        for (int k = 0; k < 256; k += 4) {
            const float4 h4 = *reinterpret_cast<const float4*>(hrow + k);
            const float4 w0 = wrp[(k + 0) * 32];
            const float4 w1 = wrp[(k + 1) * 32];
            const float4 w2 = wrp[(k + 2) * 32];
            const float4 w3 = wrp[(k + 3) * 32];
            acc.x = fmaf(h4.x, w0.x, acc.x);
            acc.y = fmaf(h4.x, w0.y, acc.y);
            acc.z = fmaf(h4.x, w0.z, acc.z);
            acc.w = fmaf(h4.x, w0.w, acc.w);
            acc.x = fmaf(h4.y, w1.x, acc.x);
            acc.y = fmaf(h4.y, w1.y, acc.y);
            acc.z = fmaf(h4.y, w1.z, acc.z);
            acc.w = fmaf(h4.y, w1.w, acc.w);
            acc.x = fmaf(h4.z, w2.x, acc.x);
            acc.y = fmaf(h4.z, w2.y, acc.y);
            acc.z = fmaf(h4.z, w2.z, acc.z);
            acc.w = fmaf(h4.z, w2.w, acc.w);
            acc.x = fmaf(h4.w, w3.x, acc.x);
            acc.y = fmaf(h4.w, w3.y, acc.y);
            acc.z = fmaf(h4.w, w3.z, acc.z);
            acc.w = fmaf(h4.w, w3.w, acc.w);
        }

        // Gates (Keras recurrent_activation=tanh per reference): order i, f, c, o
        const float gi = tanhf(acc.x);
        const float gf = tanhf(acc.y);
        const float gc = tanhf(acc.z);
        const float go = tanhf(acc.w);
        const float cn = fmaf(gf, cst, gi * gc);
        const float hn = go * tanhf(cn);

        const bool  mk   = m_s[(b << 9) + t] != 0;
        const float hold = hrow[ug];
        const float hv   = mk ? hn : hold;
        cst = mk ? cn : cst;

        // hs output (backward direction naturally lands at original index t)
        out[((size_t)b_global * 512 + t) * 512 + (dir << 8) + ug] = hv;
        hlast = hv;

        // Broadcast h_new to all 8 CTAs' next-buffer (incl. self) via DSMEM
        const int nxt = cur ^ 1;
#pragma unroll
        for (int r = 0; r < 8; r++)
            st_cluster_f32(nxt ? r1[r] : r0[r], hv);

        CLUSTER_SYNC();   // release DSMEM stores, step boundary
        cur = nxt;
    }

    // Final state_h (h after last processed step, mask-carried)
    out[16777216 + (size_t)b_global * 512 + (dir << 8) + ug] = hlast;
}

// ---------------------------------------------------------------------------
// Launch
// ---------------------------------------------------------------------------
extern "C" void kernel_launch(void* const* d_in, const int* in_sizes, int n_in,
                              void* d_out, int out_size)
{
    const float* x    = (const float*)d_in[0];
    const float* Wk_f = (const float*)d_in[1];
    const float* Wr_f = (const float*)d_in[2];
    const float* b_f  = (const float*)d_in[3];
    const float* Wk_b = (const float*)d_in[4];
    const float* Wr_b = (const float*)d_in[5];
    const float* b_b  = (const float*)d_in[6];
    float* out = (float*)d_out;

    mask_kernel<<<4096, 256>>>(x);

    dim3 gg(256, 16);   // M/128 x N/128
    gemm_kernel<<<gg, 256>>>(x, Wk_f, Wk_b, b_f, b_b);

    cudaFuncSetAttribute(lstm_rec_kernel,
                         cudaFuncAttributeMaxDynamicSharedMemorySize, REC_SMEM_BYTES);
    lstm_rec_kernel<<<128, 256, REC_SMEM_BYTES>>>(Wr_f, Wr_b, out);
}

// round 3
// speedup vs baseline: 1.1984x; 1.1984x over previous
#include <cuda_runtime.h>
#include <cuda_bf16.h>
#include <cstdint>
#include <cmath>

// Problem: B=64, T=512, E=256, U=256, bidirectional LSTM (all-tanh), mask carry.

// ---------------------------------------------------------------------------
// Device scratch
// ---------------------------------------------------------------------------
__device__ float g_Z[2ull * 512 * 64 * 1024];                  // [dir][t][b][u*4+g]
__device__ unsigned char g_mask[64 * 512];                     // [b][t]
__device__ __align__(16) __nv_bfloat16 g_Xhi[32768ull * 256];  // [m=t*64+b][k]
__device__ __align__(16) __nv_bfloat16 g_Xlo[32768ull * 256];
__device__ __align__(16) __nv_bfloat16 g_Whi[2ull * 1024 * 256]; // [dir][q=u*4+g][k]
__device__ __align__(16) __nv_bfloat16 g_Wlo[2ull * 1024 * 256];

// ---------------------------------------------------------------------------
// Small PTX helpers (family-level features only: sm_80/sm_90/sm_100 base)
// ---------------------------------------------------------------------------
__device__ __forceinline__ uint32_t smem_u32(const void* p)
{
    uint32_t a;
    asm("{ .reg .u64 t; cvta.to.shared.u64 t, %1; cvt.u32.u64 %0, t; }"
        : "=r"(a) : "l"(p));
    return a;
}

#define CP_ASYNC16(dst, src) \
    asm volatile("cp.async.cg.shared.global [%0], [%1], 16;" \
                 :: "r"(dst), "l"(src) : "memory")
#define CP_ASYNC_COMMIT() asm volatile("cp.async.commit_group;" ::: "memory")
#define CP_ASYNC_WAIT(n)  asm volatile("cp.async.wait_group %0;" :: "n"(n) : "memory")

__device__ __forceinline__ void ldm4(uint32_t* r, uint32_t addr)
{
    asm volatile("ldmatrix.sync.aligned.m8n8.x4.shared.b16 {%0,%1,%2,%3}, [%4];"
                 : "=r"(r[0]), "=r"(r[1]), "=r"(r[2]), "=r"(r[3]) : "r"(addr));
}

__device__ __forceinline__ void mma16816(float* c, const uint32_t* a,
                                         uint32_t b0, uint32_t b1)
{
    asm volatile(
        "mma.sync.aligned.m16n8k16.row.col.f32.bf16.bf16.f32 "
        "{%0,%1,%2,%3}, {%4,%5,%6,%7}, {%8,%9}, {%0,%1,%2,%3};"
        : "+f"(c[0]), "+f"(c[1]), "+f"(c[2]), "+f"(c[3])
        : "r"(a[0]), "r"(a[1]), "r"(a[2]), "r"(a[3]), "r"(b0), "r"(b1));
}

// ---------------------------------------------------------------------------
// Mask kernel: mask[b][t] = any(x[b,t,:] != 0)
// ---------------------------------------------------------------------------
__global__ void mask_kernel(const float* __restrict__ x)
{
    int gw   = (blockIdx.x * blockDim.x + threadIdx.x) >> 5;
    int lane = threadIdx.x & 31;
    if (gw >= 64 * 512) return;
    const float4* p = reinterpret_cast<const float4*>(x + (size_t)gw * 256);
    float4 a = p[lane];
    float4 b = p[lane + 32];
    bool nz = (a.x != 0.f) || (a.y != 0.f) || (a.z != 0.f) || (a.w != 0.f) ||
              (b.x != 0.f) || (b.y != 0.f) || (b.z != 0.f) || (b.w != 0.f);
    unsigned m = __ballot_sync(0xffffffffu, nz);
    if (lane == 0) g_mask[gw] = (m != 0u) ? 1 : 0;
}

// ---------------------------------------------------------------------------
// Converters: fp32 -> (hi, lo) bf16 split
// ---------------------------------------------------------------------------
__device__ __forceinline__ void split_bf16(float f, __nv_bfloat16& hi, __nv_bfloat16& lo)
{
    hi = __float2bfloat16_rn(f);
    lo = __float2bfloat16_rn(f - __bfloat162float(hi));
}

__global__ __launch_bounds__(256) void convert_x_kernel(const float* __restrict__ x)
{
    uint32_t idx = blockIdx.x * 256u + threadIdx.x;   // 2,097,152 total
    int m = idx >> 6, q = idx & 63;
    int b = m & 63, t = m >> 6;
    float4 v = *reinterpret_cast<const float4*>(x + ((size_t)b * 512 + t) * 256 + q * 4);
    __nv_bfloat16 h0, h1, h2, h3, l0, l1, l2, l3;
    split_bf16(v.x, h0, l0);
    split_bf16(v.y, h1, l1);
    split_bf16(v.z, h2, l2);
    split_bf16(v.w, h3, l3);
    __nv_bfloat162 hp0(h0, h1), hp1(h2, h3), lp0(l0, l1), lp1(l2, l3);
    uint2 hv, lv;
    hv.x = *reinterpret_cast<uint32_t*>(&hp0);
    hv.y = *reinterpret_cast<uint32_t*>(&hp1);
    lv.x = *reinterpret_cast<uint32_t*>(&lp0);
    lv.y = *reinterpret_cast<uint32_t*>(&lp1);
    *reinterpret_cast<uint2*>(g_Xhi + (size_t)m * 256 + q * 4) = hv;
    *reinterpret_cast<uint2*>(g_Xlo + (size_t)m * 256 + q * 4) = lv;
}

__global__ __launch_bounds__(256) void convert_w_kernel(
    const float* __restrict__ Wk_f, const float* __restrict__ Wk_b)
{
    uint32_t idx = blockIdx.x * 256u + threadIdx.x;   // 524,288 total
    int dir = idx >> 18;
    uint32_t rem = idx & 0x3FFFFu;
    int q = rem >> 8, k = rem & 255;
    int u = q >> 2, g = q & 3;
    float v = (dir ? Wk_b : Wk_f)[k * 1024 + g * 256 + u];
    __nv_bfloat16 hi, lo;
    split_bf16(v, hi, lo);
    g_Whi[idx] = hi;
    g_Wlo[idx] = lo;
}

// ---------------------------------------------------------------------------
// Input GEMM via mma.sync bf16 split-3:  Z = x @ Wk + bias  -> g_Z
// Grid (256, 16): blockIdx.x = M-tile (128 rows, m = t*64+b),
//                 blockIdx.y = nt: dir = nt>>3, q0 = (nt&7)*128.
// CTA tile 128(M) x 128(q), K chunks of 64, double-buffered via cp.async.
// SMEM stage (64 KB): Ahi 16K | Alo 16K | Bhi 16K | Blo 16K, rows 128 B,
// SW128 swizzle: off(r, kb) = r*128 + (kb ^ ((r&7)*16)).
// Warp grid 4x2: warp tile 32(M) x 64(q).  TN mma.sync m16n8k16.
// ---------------------------------------------------------------------------
#define GEMM_STAGE_BYTES 65536
#define GEMM_SMEM_BYTES  (2 * GEMM_STAGE_BYTES + 1024)

__global__ __launch_bounds__(256, 1) void gemm_mma_kernel(
    const float* __restrict__ b_f, const float* __restrict__ b_b)
{
    extern __shared__ char smc[];
    char* stages = smc;                                    // 2 x 64 KB
    float* bias_s = reinterpret_cast<float*>(smc + 2 * GEMM_STAGE_BYTES);
    const uint32_t st_u32 = smem_u32(stages);

    const int tid  = threadIdx.x;
    const int wid  = tid >> 5, lane = tid & 31;
    const int wm   = wid & 3, wn = wid >> 2;               // warp grid 4x2
    const int mt   = blockIdx.x * 128;
    const int nt   = blockIdx.y;
    const int dir  = nt >> 3;
    const int q0   = (nt & 7) * 128;

    if (tid < 128) {
        const int q = q0 + tid;
        bias_s[tid] = (dir ? b_b : b_f)[(q & 3) * 256 + (q >> 2)];
    }

    const char* srcs[4] = {
        reinterpret_cast<const char*>(g_Xhi),
        reinterpret_cast<const char*>(g_Xlo),
        reinterpret_cast<const char*>(g_Whi),
        reinterpret_cast<const char*>(g_Wlo)
    };

    // --- async chunk loader: 4 regions x 128 rows x 8 x 16B -------------
    auto load_chunk = [&](int c, int s) {
        const uint32_t sb = st_u32 + (uint32_t)s * GEMM_STAGE_BYTES;
        const int koff = c * 128;                          // bytes into 512 B row
#pragma unroll
        for (int it = 0; it < 16; it++) {
            const int idx    = it * 256 + tid;             // 0..4095
            const int region = idx >> 10;                  // 0..3
            const int r      = (idx >> 3) & 127;
            const int q4     = idx & 7;
            const int grow   = (region < 2) ? (mt + r) : (dir * 1024 + q0 + r);
            const char* src  = srcs[region] + (size_t)grow * 512 + koff + q4 * 16;
            const uint32_t dst = sb + region * 16384 + r * 128
                               + (((uint32_t)q4 * 16) ^ (((uint32_t)(r & 7)) * 16));
            CP_ASYNC16(dst, src);
        }
    };

    // --- fragment address precompute ------------------------------------
    const int grp = lane >> 3, lr = lane & 7;
    const uint32_t xr16 = (uint32_t)lr * 16;
    const uint32_t koffA = (uint32_t)(grp >> 1) * 16;      // A: kb-half from grp>>1
    const uint32_t koffB = (uint32_t)(grp & 1) * 16;       // B: kb-half from grp&1
    uint32_t baseA[2], baseB[4];
#pragma unroll
    for (int i = 0; i < 2; i++) {
        const int rowA = wm * 32 + i * 16 + lr + (grp & 1) * 8;
        baseA[i] = (uint32_t)rowA * 128;
    }
#pragma unroll
    for (int j2 = 0; j2 < 4; j2++) {
        const int rowB = wn * 64 + j2 * 16 + lr + (grp >> 1) * 8;
        baseB[j2] = (uint32_t)rowB * 128;
    }

    float acc[2][8][4];
#pragma unroll
    for (int i = 0; i < 2; i++)
#pragma unroll
        for (int j = 0; j < 8; j++)
#pragma unroll
            for (int v = 0; v < 4; v++) acc[i][j][v] = 0.f;

    load_chunk(0, 0);
    CP_ASYNC_COMMIT();

#pragma unroll
    for (int c = 0; c < 4; c++) {
        if (c < 3) { load_chunk(c + 1, (c + 1) & 1); CP_ASYNC_COMMIT(); }
        if (c < 3) CP_ASYNC_WAIT(1); else CP_ASYNC_WAIT(0);
        __syncthreads();

        const uint32_t sb = st_u32 + (uint32_t)(c & 1) * GEMM_STAGE_BYTES;
        const uint32_t Ah = sb, Al = sb + 16384, Bh = sb + 32768, Bl = sb + 49152;

#pragma unroll
        for (int ks = 0; ks < 4; ks++) {
            const uint32_t offA = (((uint32_t)ks * 32) + koffA) ^ xr16;
            const uint32_t offB = (((uint32_t)ks * 32) + koffB) ^ xr16;
            uint32_t ah[2][4], al[2][4], bh[4][4], bl[4][4];
#pragma unroll
            for (int i = 0; i < 2; i++) {
                ldm4(ah[i], Ah + baseA[i] + offA);
                ldm4(al[i], Al + baseA[i] + offA);
            }
#pragma unroll
            for (int j2 = 0; j2 < 4; j2++) {
                ldm4(bh[j2], Bh + baseB[j2] + offB);
                ldm4(bl[j2], Bl + baseB[j2] + offB);
            }
#pragma unroll
            for (int i = 0; i < 2; i++)
#pragma unroll
                for (int j = 0; j < 8; j++) {
                    const int j2 = j >> 1, sel = (j & 1) * 2;
                    mma16816(acc[i][j], ah[i], bh[j2][sel], bh[j2][sel + 1]);
                    mma16816(acc[i][j], ah[i], bl[j2][sel], bl[j2][sel + 1]);
                    mma16816(acc[i][j], al[i], bh[j2][sel], bh[j2][sel + 1]);
                }
        }
        __syncthreads();
    }

    // --- epilogue: bias add + store to g_Z ------------------------------
    const int mrow0 = mt + wm * 32 + (lane >> 2);
    const int qcol0 = q0 + wn * 64 + (lane & 3) * 2;
#pragma unroll
    for (int i = 0; i < 2; i++) {
#pragma unroll
        for (int j = 0; j < 8; j++) {
            const int q  = qcol0 + j * 8;
            const float bx = bias_s[q - q0], by = bias_s[q - q0 + 1];
#pragma unroll
            for (int half = 0; half < 2; half++) {
                const int m  = mrow0 + i * 16 + half * 8;
                const int bb = m & 63, tt = m >> 6;
                float2 v;
                v.x = acc[i][j][half * 2 + 0] + bx;
                v.y = acc[i][j][half * 2 + 1] + by;
                *reinterpret_cast<float2*>(
                    g_Z + (((size_t)dir * 512 + tt) * 64 + bb) * 1024 + q) = v;
            }
        }
    }
}

// ---------------------------------------------------------------------------
// Recurrence: 128 CTAs = 2 dirs x 8 batch-groups x 8 cluster ranks.
// Wr slice (128 KB) pinned in SMEM; h exchanged per step via DSMEM stores +
// barrier.cluster. Inner product uses packed fma.rn.f32x2 (halves FMA issue).
// ---------------------------------------------------------------------------
__device__ __forceinline__ uint32_t mapa_rank(uint32_t addr, uint32_t rank)
{
    uint32_t r;
    asm("mapa.shared::cluster.u32 %0, %1, %2;" : "=r"(r) : "r"(addr), "r"(rank));
    return r;
}
__device__ __forceinline__ void st_cluster_f32(uint32_t addr, float v)
{
    asm volatile("st.shared::cluster.f32 [%0], %1;" :: "r"(addr), "f"(v) : "memory");
}
#define CLUSTER_SYNC() do { \
    asm volatile("barrier.cluster.arrive.aligned;" ::: "memory"); \
    asm volatile("barrier.cluster.wait.aligned;"   ::: "memory"); \
} while (0)

__device__ __forceinline__ uint64_t packf2(float a, float b)
{
    uint64_t r;
    asm("mov.b64 %0, {%1, %2};" : "=l"(r) : "f"(a), "f"(b));
    return r;
}
__device__ __forceinline__ void unpackf2(uint64_t v, float& a, float& b)
{
    asm("mov.b64 {%0, %1}, %2;" : "=f"(a), "=f"(b) : "l"(v));
}
__device__ __forceinline__ uint64_t fmaf2(uint64_t a, uint64_t b, uint64_t c)
{
    uint64_t d;
    asm("fma.rn.f32x2 %0, %1, %2, %3;" : "=l"(d) : "l"(a), "l"(b), "l"(c));
    return d;
}

#define REC_SMEM_BYTES ((32768 + 4160) * 4 + 4096)

__global__ void __cluster_dims__(8, 1, 1) __launch_bounds__(256, 1)
lstm_rec_kernel(const float* __restrict__ Wr_f, const float* __restrict__ Wr_b,
                float* __restrict__ out)
{
    extern __shared__ float sm[];
    float* Wr_s = sm;                       // [k][ul][gate]: 32768 floats
    float* h_s  = sm + 32768;               // [2][8][260]
    unsigned char* m_s = reinterpret_cast<unsigned char*>(sm + 32768 + 4160);

    const int tid  = threadIdx.x;
    const int bx   = blockIdx.x;
    const int dir  = bx >> 6;
    const int rank = bx & 7;
    const int bg   = (bx & 63) >> 3;
    const int w    = tid >> 5, lane = tid & 31;
    const int b    = lane & 7, uoff = lane >> 3;
    const int ul   = w * 4 + uoff;
    const int ug   = (rank << 5) + ul;
    const int b_global = (bg << 3) + b;

    const float* Wr = dir ? Wr_b : Wr_f;
    for (int i = tid; i < 256 * 32; i += 256) {
        const int k = i >> 5, ux = i & 31;
        const int u = (rank << 5) + ux;
        float4 v;
        v.x = Wr[k * 1024 + u];
        v.y = Wr[k * 1024 + 256 + u];
        v.z = Wr[k * 1024 + 512 + u];
        v.w = Wr[k * 1024 + 768 + u];
        reinterpret_cast<float4*>(Wr_s)[(k << 5) + ux] = v;
    }
    for (int i = tid; i < 8 * 512; i += 256)
        m_s[i] = g_mask[((bg << 3) + (i >> 9)) * 512 + (i & 511)];
    for (int i = tid; i < 2 * 8 * 260; i += 256) h_s[i] = 0.f;

    const uint32_t base = smem_u32(h_s);
    const uint32_t l0 = base + ((uint32_t)((0 * 8 + b) * 260 + ug) << 2);
    const uint32_t l1 = base + ((uint32_t)((1 * 8 + b) * 260 + ug) << 2);
    uint32_t r0[8], r1[8];
#pragma unroll
    for (int r = 0; r < 8; r++) { r0[r] = mapa_rank(l0, r); r1[r] = mapa_rank(l1, r); }

    CLUSTER_SYNC();

    float cst = 0.f;
    float hlast = 0.f;
    int cur = 0;

    const float4* Z4 = reinterpret_cast<const float4*>(g_Z);
    const int t0 = dir ? 511 : 0;
    float4 znext = __ldg(&Z4[(((size_t)dir * 512 + t0) * 64 + b_global) * 256 + ug]);

    for (int step = 0; step < 512; step++) {
        const int t = dir ? (511 - step) : step;
        const float4 zin = znext;
        if (step < 511) {
            const int tn = dir ? (510 - step) : (step + 1);
            znext = __ldg(&Z4[(((size_t)dir * 512 + tn) * 64 + b_global) * 256 + ug]);
        }

        uint64_t acc01 = packf2(zin.x, zin.y);
        uint64_t acc23 = packf2(zin.z, zin.w);

        const float*      hrow = h_s + (cur * 8 + b) * 260;
        const ulonglong2* wrp  = reinterpret_cast<const ulonglong2*>(Wr_s) + ul;
#pragma unroll 8
        for (int k = 0; k < 256; k += 4) {
            const float4 h4 = *reinterpret_cast<const float4*>(hrow + k);
            const ulonglong2 w0 = wrp[(k + 0) * 32];
            const ulonglong2 w1 = wrp[(k + 1) * 32];
            const ulonglong2 w2 = wrp[(k + 2) * 32];
            const ulonglong2 w3 = wrp[(k + 3) * 32];
            uint64_t hh;
            hh = packf2(h4.x, h4.x);
            acc01 = fmaf2(hh, w0.x, acc01);
            acc23 = fmaf2(hh, w0.y, acc23);
            hh = packf2(h4.y, h4.y);
            acc01 = fmaf2(hh, w1.x, acc01);
            acc23 = fmaf2(hh, w1.y, acc23);
            hh = packf2(h4.z, h4.z);
            acc01 = fmaf2(hh, w2.x, acc01);
            acc23 = fmaf2(hh, w2.y, acc23);
            hh = packf2(h4.w, h4.w);
            acc01 = fmaf2(hh, w3.x, acc01);
            acc23 = fmaf2(hh, w3.y, acc23);
        }

        float zx, zy, zz, zw;
        unpackf2(acc01, zx, zy);
        unpackf2(acc23, zz, zw);

        const float gi = tanhf(zx);
        const float gf = tanhf(zy);
        const float gc = tanhf(zz);
        const float go = tanhf(zw);
        const float cn = fmaf(gf, cst, gi * gc);
        const float hn = go * tanhf(cn);

        const bool  mk   = m_s[(b << 9) + t] != 0;
        const float hold = hrow[ug];
        const float hv   = mk ? hn : hold;
        cst = mk ? cn : cst;

        out[((size_t)b_global * 512 + t) * 512 + (dir << 8) + ug] = hv;
        hlast = hv;

        const int nxt = cur ^ 1;
#pragma unroll
        for (int r = 0; r < 8; r++)
            st_cluster_f32(nxt ? r1[r] : r0[r], hv);

        CLUSTER_SYNC();
        cur = nxt;
    }

    out[16777216 + (size_t)b_global * 512 + (dir << 8) + ug] = hlast;
}

// ---------------------------------------------------------------------------
// Launch
// ---------------------------------------------------------------------------
extern "C" void kernel_launch(void* const* d_in, const int* in_sizes, int n_in,
                              void* d_out, int out_size)
{
    const float* x    = (const float*)d_in[0];
    const float* Wk_f = (const float*)d_in[1];
    const float* Wr_f = (const float*)d_in[2];
    const float* b_f  = (const float*)d_in[3];
    const float* Wk_b = (const float*)d_in[4];
    const float* Wr_b = (const float*)d_in[5];
    const float* b_b  = (const float*)d_in[6];
    float* out = (float*)d_out;

    mask_kernel<<<4096, 256>>>(x);
    convert_x_kernel<<<8192, 256>>>(x);
    convert_w_kernel<<<2048, 256>>>(Wk_f, Wk_b);

    cudaFuncSetAttribute(gemm_mma_kernel,
                         cudaFuncAttributeMaxDynamicSharedMemorySize, GEMM_SMEM_BYTES);
    dim3 gg(256, 16);
    gemm_mma_kernel<<<gg, 256, GEMM_SMEM_BYTES>>>(b_f, b_b);

    cudaFuncSetAttribute(lstm_rec_kernel,
                         cudaFuncAttributeMaxDynamicSharedMemorySize, REC_SMEM_BYTES);
    lstm_rec_kernel<<<128, 256, REC_SMEM_BYTES>>>(Wr_f, Wr_b, out);
}

// round 4
// speedup vs baseline: 1.6923x; 1.4122x over previous
#include <cuda_runtime.h>
#include <cuda_bf16.h>
#include <cstdint>
#include <cmath>

// Problem: B=64, T=512, E=256, U=256, bidirectional LSTM (all-tanh), mask carry.

// ---------------------------------------------------------------------------
// Device scratch
// ---------------------------------------------------------------------------
__device__ float g_Z[2ull * 512 * 64 * 1024];                  // [dir][t][b][u*4+g]
__device__ unsigned char g_mask[64 * 512];                     // [b][t]
__device__ __align__(16) __nv_bfloat16 g_Xhi[32768ull * 256];  // [m=t*64+b][k]
__device__ __align__(16) __nv_bfloat16 g_Xlo[32768ull * 256];
__device__ __align__(16) __nv_bfloat16 g_Whi[2ull * 1024 * 256]; // [dir][q=u*4+g][k]
__device__ __align__(16) __nv_bfloat16 g_Wlo[2ull * 1024 * 256];

// ---------------------------------------------------------------------------
// Small PTX helpers (family-level features only)
// ---------------------------------------------------------------------------
__device__ __forceinline__ uint32_t smem_u32(const void* p)
{
    uint32_t a;
    asm("{ .reg .u64 t; cvta.to.shared.u64 t, %1; cvt.u32.u64 %0, t; }"
        : "=r"(a) : "l"(p));
    return a;
}

#define CP_ASYNC16(dst, src) \
    asm volatile("cp.async.cg.shared.global [%0], [%1], 16;" \
                 :: "r"(dst), "l"(src) : "memory")
#define CP_ASYNC_COMMIT() asm volatile("cp.async.commit_group;" ::: "memory")
#define CP_ASYNC_WAIT(n)  asm volatile("cp.async.wait_group %0;" :: "n"(n) : "memory")

__device__ __forceinline__ void ldm4(uint32_t* r, uint32_t addr)
{
    asm volatile("ldmatrix.sync.aligned.m8n8.x4.shared.b16 {%0,%1,%2,%3}, [%4];"
                 : "=r"(r[0]), "=r"(r[1]), "=r"(r[2]), "=r"(r[3]) : "r"(addr));
}

__device__ __forceinline__ void mma16816(float* c, const uint32_t* a,
                                         uint32_t b0, uint32_t b1)
{
    asm volatile(
        "mma.sync.aligned.m16n8k16.row.col.f32.bf16.bf16.f32 "
        "{%0,%1,%2,%3}, {%4,%5,%6,%7}, {%8,%9}, {%0,%1,%2,%3};"
        : "+f"(c[0]), "+f"(c[1]), "+f"(c[2]), "+f"(c[3])
        : "r"(a[0]), "r"(a[1]), "r"(a[2]), "r"(a[3]), "r"(b0), "r"(b1));
}

__device__ __forceinline__ uint64_t packf2(float a, float b)
{
    uint64_t r;
    asm("mov.b64 %0, {%1, %2};" : "=l"(r) : "f"(a), "f"(b));
    return r;
}
__device__ __forceinline__ void unpackf2(uint64_t v, float& a, float& b)
{
    asm("mov.b64 {%0, %1}, %2;" : "=f"(a), "=f"(b) : "l"(v));
}
__device__ __forceinline__ uint64_t fmaf2(uint64_t a, uint64_t b, uint64_t c)
{
    uint64_t d;
    asm("fma.rn.f32x2 %0, %1, %2, %3;" : "=l"(d) : "l"(a), "l"(b), "l"(c));
    return d;
}
__device__ __forceinline__ uint32_t mapa_rank(uint32_t addr, uint32_t rank)
{
    uint32_t r;
    asm("mapa.shared::cluster.u32 %0, %1, %2;" : "=r"(r) : "r"(addr), "r"(rank));
    return r;
}
__device__ __forceinline__ void st_cluster_f32(uint32_t addr, float v)
{
    asm volatile("st.shared::cluster.f32 [%0], %1;" :: "r"(addr), "f"(v) : "memory");
}
#define CLUSTER_SYNC() do { \
    asm volatile("barrier.cluster.arrive.aligned;" ::: "memory"); \
    asm volatile("barrier.cluster.wait.aligned;"   ::: "memory"); \
} while (0)

// ---------------------------------------------------------------------------
// Mask kernel: mask[b][t] = any(x[b,t,:] != 0)
// ---------------------------------------------------------------------------
__global__ void mask_kernel(const float* __restrict__ x)
{
    int gw   = (blockIdx.x * blockDim.x + threadIdx.x) >> 5;
    int lane = threadIdx.x & 31;
    if (gw >= 64 * 512) return;
    const float4* p = reinterpret_cast<const float4*>(x + (size_t)gw * 256);
    float4 a = p[lane];
    float4 b = p[lane + 32];
    bool nz = (a.x != 0.f) || (a.y != 0.f) || (a.z != 0.f) || (a.w != 0.f) ||
              (b.x != 0.f) || (b.y != 0.f) || (b.z != 0.f) || (b.w != 0.f);
    unsigned m = __ballot_sync(0xffffffffu, nz);
    if (lane == 0) g_mask[gw] = (m != 0u) ? 1 : 0;
}

// ---------------------------------------------------------------------------
// Converters: fp32 -> (hi, lo) bf16 split
// ---------------------------------------------------------------------------
__device__ __forceinline__ void split_bf16(float f, __nv_bfloat16& hi, __nv_bfloat16& lo)
{
    hi = __float2bfloat16_rn(f);
    lo = __float2bfloat16_rn(f - __bfloat162float(hi));
}

__global__ __launch_bounds__(256) void convert_x_kernel(const float* __restrict__ x)
{
    uint32_t idx = blockIdx.x * 256u + threadIdx.x;   // 2,097,152 total
    int m = idx >> 6, q = idx & 63;
    int b = m & 63, t = m >> 6;
    float4 v = *reinterpret_cast<const float4*>(x + ((size_t)b * 512 + t) * 256 + q * 4);
    __nv_bfloat16 h0, h1, h2, h3, l0, l1, l2, l3;
    split_bf16(v.x, h0, l0);
    split_bf16(v.y, h1, l1);
    split_bf16(v.z, h2, l2);
    split_bf16(v.w, h3, l3);
    __nv_bfloat162 hp0(h0, h1), hp1(h2, h3), lp0(l0, l1), lp1(l2, l3);
    uint2 hv, lv;
    hv.x = *reinterpret_cast<uint32_t*>(&hp0);
    hv.y = *reinterpret_cast<uint32_t*>(&hp1);
    lv.x = *reinterpret_cast<uint32_t*>(&lp0);
    lv.y = *reinterpret_cast<uint32_t*>(&lp1);
    *reinterpret_cast<uint2*>(g_Xhi + (size_t)m * 256 + q * 4) = hv;
    *reinterpret_cast<uint2*>(g_Xlo + (size_t)m * 256 + q * 4) = lv;
}

__global__ __launch_bounds__(256) void convert_w_kernel(
    const float* __restrict__ Wk_f, const float* __restrict__ Wk_b)
{
    uint32_t idx = blockIdx.x * 256u + threadIdx.x;   // 524,288 total
    int dir = idx >> 18;
    uint32_t rem = idx & 0x3FFFFu;
    int q = rem >> 8, k = rem & 255;
    int u = q >> 2, g = q & 3;
    float v = (dir ? Wk_b : Wk_f)[k * 1024 + g * 256 + u];
    __nv_bfloat16 hi, lo;
    split_bf16(v, hi, lo);
    g_Whi[idx] = hi;
    g_Wlo[idx] = lo;
}

// ---------------------------------------------------------------------------
// Input GEMM via mma.sync bf16 split-3 (unchanged from R3: 255us, tensor 67%)
// ---------------------------------------------------------------------------
#define GEMM_STAGE_BYTES 65536
#define GEMM_SMEM_BYTES  (2 * GEMM_STAGE_BYTES + 1024)

__global__ __launch_bounds__(256, 1) void gemm_mma_kernel(
    const float* __restrict__ b_f, const float* __restrict__ b_b)
{
    extern __shared__ char smc[];
    char* stages = smc;
    float* bias_s = reinterpret_cast<float*>(smc + 2 * GEMM_STAGE_BYTES);
    const uint32_t st_u32 = smem_u32(stages);

    const int tid  = threadIdx.x;
    const int wid  = tid >> 5, lane = tid & 31;
    const int wm   = wid & 3, wn = wid >> 2;
    const int mt   = blockIdx.x * 128;
    const int nt   = blockIdx.y;
    const int dir  = nt >> 3;
    const int q0   = (nt & 7) * 128;

    if (tid < 128) {
        const int q = q0 + tid;
        bias_s[tid] = (dir ? b_b : b_f)[(q & 3) * 256 + (q >> 2)];
    }

    const char* srcs[4] = {
        reinterpret_cast<const char*>(g_Xhi),
        reinterpret_cast<const char*>(g_Xlo),
        reinterpret_cast<const char*>(g_Whi),
        reinterpret_cast<const char*>(g_Wlo)
    };

    auto load_chunk = [&](int c, int s) {
        const uint32_t sb = st_u32 + (uint32_t)s * GEMM_STAGE_BYTES;
        const int koff = c * 128;
#pragma unroll
        for (int it = 0; it < 16; it++) {
            const int idx    = it * 256 + tid;
            const int region = idx >> 10;
            const int r      = (idx >> 3) & 127;
            const int q4     = idx & 7;
            const int grow   = (region < 2) ? (mt + r) : (dir * 1024 + q0 + r);
            const char* src  = srcs[region] + (size_t)grow * 512 + koff + q4 * 16;
            const uint32_t dst = sb + region * 16384 + r * 128
                               + (((uint32_t)q4 * 16) ^ (((uint32_t)(r & 7)) * 16));
            CP_ASYNC16(dst, src);
        }
    };

    const int grp = lane >> 3, lr = lane & 7;
    const uint32_t xr16 = (uint32_t)lr * 16;
    const uint32_t koffA = (uint32_t)(grp >> 1) * 16;
    const uint32_t koffB = (uint32_t)(grp & 1) * 16;
    uint32_t baseA[2], baseB[4];
#pragma unroll
    for (int i = 0; i < 2; i++) {
        const int rowA = wm * 32 + i * 16 + lr + (grp & 1) * 8;
        baseA[i] = (uint32_t)rowA * 128;
    }
#pragma unroll
    for (int j2 = 0; j2 < 4; j2++) {
        const int rowB = wn * 64 + j2 * 16 + lr + (grp >> 1) * 8;
        baseB[j2] = (uint32_t)rowB * 128;
    }

    float acc[2][8][4];
#pragma unroll
    for (int i = 0; i < 2; i++)
#pragma unroll
        for (int j = 0; j < 8; j++)
#pragma unroll
            for (int v = 0; v < 4; v++) acc[i][j][v] = 0.f;

    load_chunk(0, 0);
    CP_ASYNC_COMMIT();

#pragma unroll
    for (int c = 0; c < 4; c++) {
        if (c < 3) { load_chunk(c + 1, (c + 1) & 1); CP_ASYNC_COMMIT(); }
        if (c < 3) CP_ASYNC_WAIT(1); else CP_ASYNC_WAIT(0);
        __syncthreads();

        const uint32_t sb = st_u32 + (uint32_t)(c & 1) * GEMM_STAGE_BYTES;
        const uint32_t Ah = sb, Al = sb + 16384, Bh = sb + 32768, Bl = sb + 49152;

#pragma unroll
        for (int ks = 0; ks < 4; ks++) {
            const uint32_t offA = (((uint32_t)ks * 32) + koffA) ^ xr16;
            const uint32_t offB = (((uint32_t)ks * 32) + koffB) ^ xr16;
            uint32_t ah[2][4], al[2][4], bh[4][4], bl[4][4];
#pragma unroll
            for (int i = 0; i < 2; i++) {
                ldm4(ah[i], Ah + baseA[i] + offA);
                ldm4(al[i], Al + baseA[i] + offA);
            }
#pragma unroll
            for (int j2 = 0; j2 < 4; j2++) {
                ldm4(bh[j2], Bh + baseB[j2] + offB);
                ldm4(bl[j2], Bl + baseB[j2] + offB);
            }
#pragma unroll
            for (int i = 0; i < 2; i++)
#pragma unroll
                for (int j = 0; j < 8; j++) {
                    const int j2 = j >> 1, sel = (j & 1) * 2;
                    mma16816(acc[i][j], ah[i], bh[j2][sel], bh[j2][sel + 1]);
                    mma16816(acc[i][j], ah[i], bl[j2][sel], bl[j2][sel + 1]);
                    mma16816(acc[i][j], al[i], bh[j2][sel], bh[j2][sel + 1]);
                }
        }
        __syncthreads();
    }

    const int mrow0 = mt + wm * 32 + (lane >> 2);
    const int qcol0 = q0 + wn * 64 + (lane & 3) * 2;
#pragma unroll
    for (int i = 0; i < 2; i++) {
#pragma unroll
        for (int j = 0; j < 8; j++) {
            const int q  = qcol0 + j * 8;
            const float bx = bias_s[q - q0], by = bias_s[q - q0 + 1];
#pragma unroll
            for (int half = 0; half < 2; half++) {
                const int m  = mrow0 + i * 16 + half * 8;
                const int bb = m & 63, tt = m >> 6;
                float2 v;
                v.x = acc[i][j][half * 2 + 0] + bx;
                v.y = acc[i][j][half * 2 + 1] + by;
                *reinterpret_cast<float2*>(
                    g_Z + (((size_t)dir * 512 + tt) * 64 + bb) * 1024 + q) = v;
            }
        }
    }
}

// ---------------------------------------------------------------------------
// Recurrence v2 — dense-LDS, split-k across warps.
// 128 CTAs = 2 dirs x 8 batch-groups x 8 cluster ranks (cluster of 8).
// SMEM floats: Wr_s[256 k][128 col]      (32768)  col = u_local*4 + gate
//              h_T [2][256 u][8 b]        (4096)
//              part[32 row][130 float2]   (8320)  row = warp*4 + bpair
//              mask bytes [8][512]        (4096 B)
// FMA phase: warp w covers k in [32w, 32w+32); per k: 1 dense LDS.128 of the
// 512B weight row (lane l -> cols 4l..4l+3), 2 uniform 16B h-pair loads,
// acc packed over b-pairs via fma.rn.f32x2. Then split-k reduce via SMEM,
// gates per (b,u) thread, h broadcast via DSMEM + barrier.cluster.
// ---------------------------------------------------------------------------
#define REC_WRS_F   32768
#define REC_HT_F    4096
#define REC_PART_F  8320
#define REC_SMEM_BYTES ((REC_WRS_F + REC_HT_F + REC_PART_F) * 4 + 4096)

__global__ void __cluster_dims__(8, 1, 1) __launch_bounds__(256, 1)
lstm_rec_kernel(const float* __restrict__ Wr_f, const float* __restrict__ Wr_b,
                float* __restrict__ out)
{
    extern __shared__ float sm[];
    float* Wr_s = sm;
    float* h_T  = sm + REC_WRS_F;
    float* part = sm + REC_WRS_F + REC_HT_F;
    unsigned char* m_s =
        reinterpret_cast<unsigned char*>(sm + REC_WRS_F + REC_HT_F + REC_PART_F);

    const int tid  = threadIdx.x;
    const int bx   = blockIdx.x;
    const int dir  = bx >> 6;
    const int rank = bx & 7;
    const int bg   = (bx & 63) >> 3;
    const int w    = tid >> 5, lane = tid & 31;
    // gates-phase mapping: one thread per (b, u_local)
    const int ul   = tid >> 3;          // 0..31
    const int b    = tid & 7;           // 0..7
    const int ug   = (rank << 5) + ul;  // 0..255
    const int b_global = (bg << 3) + b;

    // --- init: Wr slice (coalesced gmem reads, scattered STS) -------------
    const float* Wr = dir ? Wr_b : Wr_f;
    for (int i = tid; i < 32768; i += 256) {
        const int lul = i & 31;
        const int g   = (i >> 5) & 3;
        const int k   = i >> 7;
        Wr_s[k * 128 + lul * 4 + g] = Wr[k * 1024 + g * 256 + (rank << 5) + lul];
    }
    for (int i = tid; i < 8 * 512; i += 256)
        m_s[i] = g_mask[((bg << 3) + (i >> 9)) * 512 + (i & 511)];
    for (int i = tid; i < REC_HT_F; i += 256) h_T[i] = 0.f;

    // --- DSMEM broadcast addresses (both buffers x 8 ranks) ---------------
    const uint32_t hbase = smem_u32(h_T);
    const uint32_t l0 = hbase + ((uint32_t)(ug * 8 + b) << 2);
    const uint32_t l1 = l0 + 2048 * 4;
    uint32_t r0[8], r1[8];
#pragma unroll
    for (int r = 0; r < 8; r++) { r0[r] = mapa_rank(l0, r); r1[r] = mapa_rank(l1, r); }

    CLUSTER_SYNC();

    float cst = 0.f, hlast = 0.f;
    int cur = 0;

    const float4* Z4 = reinterpret_cast<const float4*>(g_Z);
    const int t0 = dir ? 511 : 0;
    float4 znext = __ldg(&Z4[(((size_t)dir * 512 + t0) * 64 + b_global) * 256 + ug]);

    // FMA-phase pointers (warp-based)
    const float4*     wrow0 = reinterpret_cast<const float4*>(Wr_s + (w << 5) * 128) + lane;
    const int         bp_t  = b >> 1, half = b & 1;
    // partial base for this thread's reduce reads (float index)
    float* pr = part + ((bp_t * 130) + ul * 4) * 2 + half;

    for (int step = 0; step < 512; step++) {
        const int t = dir ? (511 - step) : step;
        const float4 zin = znext;
        if (step < 511) {
            const int tn = dir ? (510 - step) : (step + 1);
            znext = __ldg(&Z4[(((size_t)dir * 512 + tn) * 64 + b_global) * 256 + ug]);
        }

        // ---- GEMM phase: k in [32w, 32w+32), 8 b x 4 cols per lane ------
        uint64_t acc[4][4];
#pragma unroll
        for (int i = 0; i < 4; i++)
#pragma unroll
            for (int j = 0; j < 4; j++) acc[i][j] = 0;

        const ulonglong2* hk =
            reinterpret_cast<const ulonglong2*>(h_T + cur * 2048 + (w << 5) * 8);
        const float4* wr = wrow0;

#pragma unroll 8
        for (int kk = 0; kk < 32; kk++) {
            const ulonglong2 hA = hk[kk * 2];        // (h0,h1),(h2,h3)
            const ulonglong2 hB = hk[kk * 2 + 1];    // (h4,h5),(h6,h7)
            const float4 wv = wr[kk * 32];
            uint64_t wd0 = packf2(wv.x, wv.x);
            uint64_t wd1 = packf2(wv.y, wv.y);
            uint64_t wd2 = packf2(wv.z, wv.z);
            uint64_t wd3 = packf2(wv.w, wv.w);
            acc[0][0] = fmaf2(hA.x, wd0, acc[0][0]);
            acc[0][1] = fmaf2(hA.x, wd1, acc[0][1]);
            acc[0][2] = fmaf2(hA.x, wd2, acc[0][2]);
            acc[0][3] = fmaf2(hA.x, wd3, acc[0][3]);
            acc[1][0] = fmaf2(hA.y, wd0, acc[1][0]);
            acc[1][1] = fmaf2(hA.y, wd1, acc[1][1]);
            acc[1][2] = fmaf2(hA.y, wd2, acc[1][2]);
            acc[1][3] = fmaf2(hA.y, wd3, acc[1][3]);
            acc[2][0] = fmaf2(hB.x, wd0, acc[2][0]);
            acc[2][1] = fmaf2(hB.x, wd1, acc[2][1]);
            acc[2][2] = fmaf2(hB.x, wd2, acc[2][2]);
            acc[2][3] = fmaf2(hB.x, wd3, acc[2][3]);
            acc[3][0] = fmaf2(hB.y, wd0, acc[3][0]);
            acc[3][1] = fmaf2(hB.y, wd1, acc[3][1]);
            acc[3][2] = fmaf2(hB.y, wd2, acc[3][2]);
            acc[3][3] = fmaf2(hB.y, wd3, acc[3][3]);
        }

        // ---- store partials: row = w*4 + bp, 130-float2 stride ----------
        {
            ulonglong2* pw = reinterpret_cast<ulonglong2*>(part) +
                             ((w << 2) * 130 + lane * 4) / 2;
#pragma unroll
            for (int bp = 0; bp < 4; bp++) {
                ulonglong2 v0; v0.x = acc[bp][0]; v0.y = acc[bp][1];
                ulonglong2 v1; v1.x = acc[bp][2]; v1.y = acc[bp][3];
                pw[bp * 65] = v0;         // 65 ull2 = 130 float2
                pw[bp * 65 + 1] = v1;
            }
        }
        __syncthreads();

        // ---- reduce + gates per (b, u_local) thread ---------------------
        float z0 = zin.x, z1 = zin.y, z2 = zin.z, z3 = zin.w;
#pragma unroll
        for (int w8 = 0; w8 < 8; w8++) {
            const float* p = pr + (w8 << 2) * 260;   // (w8*4 rows)*130 f2*2
            z0 += p[0];
            z1 += p[2];
            z2 += p[4];
            z3 += p[6];
        }

        const float gi = tanhf(z0);
        const float gf = tanhf(z1);
        const float gc = tanhf(z2);
        const float go = tanhf(z3);
        const float cn = fmaf(gf, cst, gi * gc);
        const float hn = go * tanhf(cn);

        const bool  mk   = m_s[(b << 9) + t] != 0;
        const float hold = h_T[cur * 2048 + ug * 8 + b];
        const float hv   = mk ? hn : hold;
        cst = mk ? cn : cst;

        out[((size_t)b_global * 512 + t) * 512 + (dir << 8) + ug] = hv;
        hlast = hv;

        // broadcast h to all 8 CTAs' next buffer
        const int nxt = cur ^ 1;
#pragma unroll
        for (int r = 0; r < 8; r++)
            st_cluster_f32(nxt ? r1[r] : r0[r], hv);

        CLUSTER_SYNC();
        cur = nxt;
    }

    out[16777216 + (size_t)b_global * 512 + (dir << 8) + ug] = hlast;
}

// ---------------------------------------------------------------------------
// Launch
// ---------------------------------------------------------------------------
extern "C" void kernel_launch(void* const* d_in, const int* in_sizes, int n_in,
                              void* d_out, int out_size)
{
    const float* x    = (const float*)d_in[0];
    const float* Wk_f = (const float*)d_in[1];
    const float* Wr_f = (const float*)d_in[2];
    const float* b_f  = (const float*)d_in[3];
    const float* Wk_b = (const float*)d_in[4];
    const float* Wr_b = (const float*)d_in[5];
    const float* b_b  = (const float*)d_in[6];
    float* out = (float*)d_out;

    mask_kernel<<<4096, 256>>>(x);
    convert_x_kernel<<<8192, 256>>>(x);
    convert_w_kernel<<<2048, 256>>>(Wk_f, Wk_b);

    cudaFuncSetAttribute(gemm_mma_kernel,
                         cudaFuncAttributeMaxDynamicSharedMemorySize, GEMM_SMEM_BYTES);
    dim3 gg(256, 16);
    gemm_mma_kernel<<<gg, 256, GEMM_SMEM_BYTES>>>(b_f, b_b);

    cudaFuncSetAttribute(lstm_rec_kernel,
                         cudaFuncAttributeMaxDynamicSharedMemorySize, REC_SMEM_BYTES);
    lstm_rec_kernel<<<128, 256, REC_SMEM_BYTES>>>(Wr_f, Wr_b, out);
}